// round 10
// baseline (speedup 1.0000x reference)
#include <cuda_runtime.h>
#include <cuda_bf16.h>
#include <cstdint>
#include <math.h>

// Problem constants
#define BB    2
#define TT    32
#define HH    18
#define WW    32
#define DIM   1024
#define HEADS 16
#define HD    64
#define HWP   (HH*WW)            // 576
#define MTOK  (BB*TT*HWP)        // 36864 tokens
#define EQKV  (3*HEADS*HD)       // 3072
#define EO    (HEADS*HD)         // 1024

// ---------------- scratch (device globals; no allocation allowed) ----------
__device__ float   g_qkv[(size_t)MTOK * EQKV];     // fp32 qkv
__device__ float   g_att[(size_t)MTOK * EO];       // fp32 attention out
__device__ int8_t  g_x1[(size_t)MTOK * DIM],   g_x2[(size_t)MTOK * DIM];
__device__ int8_t  g_wq1[(size_t)EQKV * DIM],  g_wq2[(size_t)EQKV * DIM];
__device__ int8_t  g_wo1[(size_t)DIM * DIM],   g_wo2[(size_t)DIM * DIM];
__device__ int8_t  g_a1[(size_t)MTOK * EO],    g_a2[(size_t)MTOK * EO];
__device__ float   g_sx[MTOK], g_swq[EQKV], g_swo[DIM], g_sa[MTOK];

// ---------------- helpers ---------------------------------------------------
__device__ __forceinline__ uint32_t smem_u32(const void* p) {
    uint32_t a;
    asm("{ .reg .u64 t; cvta.to.shared.u64 t, %1; cvt.u32.u64 %0, t; }" : "=r"(a) : "l"(p));
    return a;
}

// SW64 swizzle: 64-byte rows, 8-row/512B atom
#define SWZ64(off) ((off) ^ (((off) >> 3) & 0x30))

__device__ __forceinline__ void cp16(uint32_t saddr, const void* g) {
    asm volatile("cp.async.cg.shared.global [%0], [%1], 16;" :: "r"(saddr), "l"(g));
}
#define CP_COMMIT() asm volatile("cp.async.commit_group;" ::: "memory")
#define CP_WAIT0()  asm volatile("cp.async.wait_group 0;" ::: "memory")
#define CP_WAIT1()  asm volatile("cp.async.wait_group 1;" ::: "memory")

__device__ __forceinline__ void ldm_x4(uint32_t* r, uint32_t addr) {
    asm volatile("ldmatrix.sync.aligned.m8n8.x4.shared.b16 {%0,%1,%2,%3}, [%4];"
                 : "=r"(r[0]), "=r"(r[1]), "=r"(r[2]), "=r"(r[3]) : "r"(addr));
}
__device__ __forceinline__ void ldm_x2(uint32_t* r, uint32_t addr) {
    asm volatile("ldmatrix.sync.aligned.m8n8.x2.shared.b16 {%0,%1}, [%2];"
                 : "=r"(r[0]), "=r"(r[1]) : "r"(addr));
}

__device__ __forceinline__ void mma_s8(int* d, const uint32_t* a, const uint32_t* b) {
    asm volatile("mma.sync.aligned.m16n8k32.row.col.s32.s8.s8.s32 "
                 "{%0,%1,%2,%3}, {%4,%5,%6,%7}, {%8,%9}, {%0,%1,%2,%3};"
                 : "+r"(d[0]), "+r"(d[1]), "+r"(d[2]), "+r"(d[3])
                 : "r"(a[0]), "r"(a[1]), "r"(a[2]), "r"(a[3]), "r"(b[0]), "r"(b[1]));
}

// ---------------------------------------------------------------------------
// quant2: fp32 row (1024) -> 2 int8 limbs + per-row scale. One block per row.
// a = sa*A1 + (sa/254)*A2
// ---------------------------------------------------------------------------
__global__ void __launch_bounds__(256)
quant2_kernel(const float* __restrict__ in, int8_t* __restrict__ l1,
              int8_t* __restrict__ l2, float* __restrict__ scale)
{
    const int row = blockIdx.x;
    const int tid = threadIdx.x;
    const float* p = in + (size_t)row * 1024;
    float4 v = *(const float4*)(p + tid * 4);

    float m = fmaxf(fmaxf(fabsf(v.x), fabsf(v.y)), fmaxf(fabsf(v.z), fabsf(v.w)));
    __shared__ float smax[8];
#pragma unroll
    for (int o = 16; o > 0; o >>= 1)
        m = fmaxf(m, __shfl_xor_sync(0xffffffffu, m, o));
    if ((tid & 31) == 0) smax[tid >> 5] = m;
    __syncthreads();
    m = smax[0];
#pragma unroll
    for (int i = 1; i < 8; i++) m = fmaxf(m, smax[i]);

    const float sa = (m > 0.f ? m : 1.f) * (1.f / 127.f);
    const float inv = 1.f / sa;
    float f[4] = {v.x, v.y, v.z, v.w};
    char q1[4], q2[4];
#pragma unroll
    for (int j = 0; j < 4; j++) {
        int a1 = __float2int_rn(f[j] * inv);
        float r = fmaf((float)(-a1), sa, f[j]);
        int a2 = __float2int_rn(r * inv * 254.f);
        q1[j] = (char)a1;
        q2[j] = (char)a2;
    }
    const size_t idx = (size_t)row * 1024 + tid * 4;
    *(char4*)(l1 + idx) = make_char4(q1[0], q1[1], q1[2], q1[3]);
    *(char4*)(l2 + idx) = make_char4(q2[0], q2[1], q2[2], q2[3]);
    if (tid == 0) scale[row] = sa;
}

// ---------------------------------------------------------------------------
// int8 2-limb GEMM on IMMA: C[M,N] = sa[m]*sb[n]*(A1B1 + (A1B2+A2B1)/254) (+bias)
// CTA tile 128x128, BK=64 bytes (SW64). Stage = A1|A2|B1|B2 = 32KB, 3-stage ring.
// 8 warps (2m x 4n), warp tile 64x32. occ=1 (two int32 accumulators).
// ---------------------------------------------------------------------------
#define GBK      64
#define SUB_A2   8192
#define SUB_B1   16384
#define SUB_B2   24576
#define STAGE_SZ 32768
#define NSTAGE   3
#define GSMEM_SZ (NSTAGE * STAGE_SZ)   // 98304

__device__ __forceinline__ void fill_chunk_i8(
    int cc, uint32_t dst, int tid, int m0, int n0, int K,
    const int8_t* __restrict__ A1, const int8_t* __restrict__ A2,
    const int8_t* __restrict__ B1, const int8_t* __restrict__ B2)
{
    const int kk = cc * GBK;
#pragma unroll
    for (int i = 0; i < 2; i++) {
        const int u = tid + i * 256;             // 512 16B units per sub-tile
        const int row = u >> 2, c16 = u & 3;
        const uint32_t so = SWZ64((uint32_t)(row * 64 + c16 * 16));
        const size_t aoff = (size_t)(m0 + row) * K + kk + c16 * 16;
        const size_t boff = (size_t)(n0 + row) * K + kk + c16 * 16;
        cp16(dst + so,          A1 + aoff);
        cp16(dst + SUB_A2 + so, A2 + aoff);
        cp16(dst + SUB_B1 + so, B1 + boff);
        cp16(dst + SUB_B2 + so, B2 + boff);
    }
}

__global__ void __launch_bounds__(256, 1)
gemm_i8(const int8_t* __restrict__ A1, const int8_t* __restrict__ A2,
        const int8_t* __restrict__ B1, const int8_t* __restrict__ B2,
        const float* __restrict__ sa, const float* __restrict__ sb,
        float* __restrict__ C, const float* __restrict__ bias, int N, int K)
{
    extern __shared__ char smem[];
    const uint32_t sb32 = smem_u32(smem);
    const int tid = threadIdx.x;
    const int m0 = blockIdx.y * 128;
    const int n0 = blockIdx.x * 128;
    const int lane = tid & 31;
    const int warp = tid >> 5;
    const int warp_m = warp >> 2;      // 0..1
    const int warp_n = warp & 3;       // 0..3

    int accM[4][4][4];
    int accX[4][4][4];
#pragma unroll
    for (int a = 0; a < 4; a++)
#pragma unroll
        for (int b = 0; b < 4; b++)
#pragma unroll
            for (int c = 0; c < 4; c++) { accM[a][b][c] = 0; accX[a][b][c] = 0; }

    const int kchunks = K / GBK;       // 16

    fill_chunk_i8(0, sb32, tid, m0, n0, K, A1, A2, B1, B2);
    CP_COMMIT();
    fill_chunk_i8(1, sb32 + STAGE_SZ, tid, m0, n0, K, A1, A2, B1, B2);
    CP_COMMIT();

    // ldmatrix per-thread address components (pre-swizzle, 64B rows)
    const uint32_t a_row = (uint32_t)(lane & 15);
    const uint32_t a_ko  = (uint32_t)((lane >> 4) << 4);
    const uint32_t b_row = (uint32_t)(lane & 7);
    const uint32_t b_ko  = (uint32_t)(((lane >> 3) & 1) << 4);

    for (int cc = 0; cc < kchunks; cc++) {
        if (cc + 1 < kchunks) { CP_WAIT1(); } else { CP_WAIT0(); }
        __syncthreads();
        if (cc + 2 < kchunks) {
            fill_chunk_i8(cc + 2, sb32 + (uint32_t)((cc + 2) % NSTAGE) * STAGE_SZ,
                          tid, m0, n0, K, A1, A2, B1, B2);
            CP_COMMIT();
        }
        const uint32_t st = sb32 + (uint32_t)(cc % NSTAGE) * STAGE_SZ;

#pragma unroll
        for (int ks = 0; ks < 2; ks++) {
            const uint32_t kbyte = (uint32_t)(ks * 32);
            uint32_t b1f[4][2], b2f[4][2];
#pragma unroll
            for (int nt = 0; nt < 4; nt++) {
                const uint32_t row = (uint32_t)(warp_n * 32 + nt * 8) + b_row;
                const uint32_t so = SWZ64(row * 64 + kbyte + b_ko);
                ldm_x2(b1f[nt], st + SUB_B1 + so);
                ldm_x2(b2f[nt], st + SUB_B2 + so);
            }
#pragma unroll
            for (int mt = 0; mt < 4; mt++) {
                uint32_t a1f[4], a2f[4];
                const uint32_t row = (uint32_t)(warp_m * 64 + mt * 16) + a_row;
                const uint32_t so = SWZ64(row * 64 + kbyte + a_ko);
                ldm_x4(a1f, st + so);
                ldm_x4(a2f, st + SUB_A2 + so);
#pragma unroll
                for (int nt = 0; nt < 4; nt++) {
                    mma_s8(accM[mt][nt], a1f, b1f[nt]);
                    mma_s8(accX[mt][nt], a1f, b2f[nt]);
                    mma_s8(accX[mt][nt], a2f, b1f[nt]);
                }
            }
        }
    }

    __syncthreads();

    // epilogue: C = sa*sb*(SM + SX/254) (+bias)
    const int ln4 = lane >> 2;
    const int lc2 = (lane & 3) * 2;
    const float inv254 = 1.f / 254.f;
#pragma unroll
    for (int mt = 0; mt < 4; mt++) {
        const int r0 = m0 + warp_m * 64 + mt * 16 + ln4;
        const float sa0 = sa[r0];
        const float sa1 = sa[r0 + 8];
#pragma unroll
        for (int nt = 0; nt < 4; nt++) {
            const int col = n0 + warp_n * 32 + nt * 8 + lc2;
            const float sb0 = sb[col], sb1 = sb[col + 1];
            float bx = 0.f, by = 0.f;
            if (bias) { bx = bias[col]; by = bias[col + 1]; }
            float2 v0, v1;
            v0.x = sa0 * sb0 * ((float)accM[mt][nt][0] + (float)accX[mt][nt][0] * inv254) + bx;
            v0.y = sa0 * sb1 * ((float)accM[mt][nt][1] + (float)accX[mt][nt][1] * inv254) + by;
            v1.x = sa1 * sb0 * ((float)accM[mt][nt][2] + (float)accX[mt][nt][2] * inv254) + bx;
            v1.y = sa1 * sb1 * ((float)accM[mt][nt][3] + (float)accX[mt][nt][3] * inv254) + by;
            *(float2*)(C + (size_t)r0 * N + col)       = v0;
            *(float2*)(C + (size_t)(r0 + 8) * N + col) = v1;
        }
    }
}

// ---------------------------------------------------------------------------
// Attention: one block per (sequence, head). fp32 in (qkv), fp32 out (att).
// ---------------------------------------------------------------------------
__global__ void __launch_bounds__(256)
attn_kernel(const float* __restrict__ qkv, float* __restrict__ att)
{
    const int blk  = blockIdx.x;
    const int head = blk & 15;
    const int n    = blk >> 4;
    const int b    = n / HWP;
    const int hw   = n - b * HWP;
    const size_t base_tok = (size_t)b * (TT * HWP) + hw;

    __shared__ float Qs[32][65];
    __shared__ float Ks[32][65];
    __shared__ float Vs[32][64];
    __shared__ float Ss[32][33];

    const int tid = threadIdx.x;

    for (int i = tid; i < 32 * 64; i += 256) {
        const int t = i >> 6, d = i & 63;
        const size_t tok = base_tok + (size_t)t * HWP;
        const float* p = qkv + tok * EQKV + head * HD + d;
        Qs[t][d] = p[0];
        Ks[t][d] = p[1024];
        Vs[t][d] = p[2048];
    }
    __syncthreads();

    for (int i = tid; i < 2 * 32 * 16; i += 256) {
        const int mat = i >> 9;
        const int rem = i & 511;
        const int t = rem >> 4, j = rem & 15;
        const float freq = powf(10000.0f, -(float)j / 16.0f);
        const float ang = (float)t * freq;
        const float c = cosf(ang), s = sinf(ang);
        float (*P)[65] = mat ? Ks : Qs;
        const float x0 = P[t][2 * j];
        const float x1 = P[t][2 * j + 1];
        P[t][2 * j]     = x0 * c - x1 * s;
        P[t][2 * j + 1] = x1 * c + x0 * s;
    }
    __syncthreads();

    const int r = tid >> 4, c = tid & 15;
    {
        float s00 = 0.f, s01 = 0.f, s10 = 0.f, s11 = 0.f;
#pragma unroll 16
        for (int d = 0; d < 64; d++) {
            const float q0 = Qs[2 * r][d],     q1 = Qs[2 * r + 1][d];
            const float k0 = Ks[2 * c][d],     k1 = Ks[2 * c + 1][d];
            s00 += q0 * k0; s01 += q0 * k1;
            s10 += q1 * k0; s11 += q1 * k1;
        }
        Ss[2 * r][2 * c]         = s00;
        Ss[2 * r][2 * c + 1]     = s01;
        Ss[2 * r + 1][2 * c]     = s10;
        Ss[2 * r + 1][2 * c + 1] = s11;
    }
    __syncthreads();

    const int warp = tid >> 5, lane = tid & 31;
    const float scale = 0.125f;
#pragma unroll
    for (int qi = 0; qi < 4; qi++) {
        const int q = warp * 4 + qi;
        float s = (lane <= q) ? Ss[q][lane] * scale : -INFINITY;
        float m = s;
#pragma unroll
        for (int o = 16; o > 0; o >>= 1)
            m = fmaxf(m, __shfl_xor_sync(0xffffffffu, m, o));
        const float e = expf(s - m);
        float sum = e;
#pragma unroll
        for (int o = 16; o > 0; o >>= 1)
            sum += __shfl_xor_sync(0xffffffffu, sum, o);
        Ss[q][lane] = e / sum;
    }
    __syncthreads();

    float o0[4] = {0.f, 0.f, 0.f, 0.f};
    float o1[4] = {0.f, 0.f, 0.f, 0.f};
#pragma unroll 8
    for (int k = 0; k < 32; k++) {
        const float p0 = Ss[2 * r][k];
        const float p1 = Ss[2 * r + 1][k];
#pragma unroll
        for (int j = 0; j < 4; j++) {
            const float v = Vs[k][4 * c + j];
            o0[j] += p0 * v;
            o1[j] += p1 * v;
        }
    }
#pragma unroll
    for (int i = 0; i < 2; i++) {
        const int t = 2 * r + i;
        const size_t tok = base_tok + (size_t)t * HWP;
        float* dst = att + tok * EO + head * HD + 4 * c;
        const float* src = i ? o1 : o0;
        dst[0] = src[0]; dst[1] = src[1]; dst[2] = src[2]; dst[3] = src[3];
    }
}

// ---------------------------------------------------------------------------
extern "C" void kernel_launch(void* const* d_in, const int* in_sizes, int n_in,
                              void* d_out, int out_size)
{
    const float* x     = (const float*)d_in[0];
    const float* w_qkv = (const float*)d_in[1];
    const float* w_out = (const float*)d_in[2];
    const float* b_out = (const float*)d_in[3];
    float* out = (float*)d_out;

    void *qkv_p, *att_p, *x1_p, *x2_p, *wq1_p, *wq2_p, *wo1_p, *wo2_p, *a1_p, *a2_p;
    void *sx_p, *swq_p, *swo_p, *sa_p;
    cudaGetSymbolAddress(&qkv_p, g_qkv);  cudaGetSymbolAddress(&att_p, g_att);
    cudaGetSymbolAddress(&x1_p, g_x1);    cudaGetSymbolAddress(&x2_p, g_x2);
    cudaGetSymbolAddress(&wq1_p, g_wq1);  cudaGetSymbolAddress(&wq2_p, g_wq2);
    cudaGetSymbolAddress(&wo1_p, g_wo1);  cudaGetSymbolAddress(&wo2_p, g_wo2);
    cudaGetSymbolAddress(&a1_p, g_a1);    cudaGetSymbolAddress(&a2_p, g_a2);
    cudaGetSymbolAddress(&sx_p, g_sx);    cudaGetSymbolAddress(&swq_p, g_swq);
    cudaGetSymbolAddress(&swo_p, g_swo);  cudaGetSymbolAddress(&sa_p, g_sa);

    float* qkv = (float*)qkv_p;
    float* att = (float*)att_p;

    cudaFuncSetAttribute(gemm_i8, cudaFuncAttributeMaxDynamicSharedMemorySize, GSMEM_SZ);

    // 0) quantize x, w_qkv, w_out into 2-limb int8 + row scales
    quant2_kernel<<<MTOK, 256>>>(x,     (int8_t*)x1_p,  (int8_t*)x2_p,  (float*)sx_p);
    quant2_kernel<<<EQKV, 256>>>(w_qkv, (int8_t*)wq1_p, (int8_t*)wq2_p, (float*)swq_p);
    quant2_kernel<<<DIM,  256>>>(w_out, (int8_t*)wo1_p, (int8_t*)wo2_p, (float*)swo_p);

    // 1) QKV projection: [36864,1024] x [3072,1024]^T -> fp32 qkv
    {
        dim3 grid(EQKV / 128, MTOK / 128);
        gemm_i8<<<grid, 256, GSMEM_SZ>>>((int8_t*)x1_p, (int8_t*)x2_p,
                                         (int8_t*)wq1_p, (int8_t*)wq2_p,
                                         (float*)sx_p, (float*)swq_p,
                                         qkv, nullptr, EQKV, DIM);
    }
    // 2) RoPE + causal attention -> fp32 att
    attn_kernel<<<(BB * HWP) * HEADS, 256>>>(qkv, att);

    // 3) quantize attention output
    quant2_kernel<<<MTOK, 256>>>(att, (int8_t*)a1_p, (int8_t*)a2_p, (float*)sa_p);

    // 4) Output projection + bias
    {
        dim3 grid(DIM / 128, MTOK / 128);
        gemm_i8<<<grid, 256, GSMEM_SZ>>>((int8_t*)a1_p, (int8_t*)a2_p,
                                         (int8_t*)wo1_p, (int8_t*)wo2_p,
                                         (float*)sa_p, (float*)swo_p,
                                         out, b_out, DIM, DIM);
    }
}

// round 11
// speedup vs baseline: 2.3873x; 2.3873x over previous
#include <cuda_runtime.h>
#include <cuda_bf16.h>
#include <cstdint>
#include <math.h>

// Problem constants
#define BB    2
#define TT    32
#define HH    18
#define WW    32
#define DIM   1024
#define HEADS 16
#define HD    64
#define HWP   (HH*WW)            // 576
#define MTOK  (BB*TT*HWP)        // 36864 tokens
#define EQKV  (3*HEADS*HD)       // 3072
#define EO    (HEADS*HD)         // 1024

// ---------------- scratch (device globals; no allocation allowed) ----------
__device__ float          g_qkv[(size_t)MTOK * EQKV];
__device__ __nv_bfloat16  g_x_hi[(size_t)MTOK * DIM];
__device__ __nv_bfloat16  g_x_lo[(size_t)MTOK * DIM];
__device__ __nv_bfloat16  g_wqkv_hi[(size_t)EQKV * DIM];
__device__ __nv_bfloat16  g_wqkv_lo[(size_t)EQKV * DIM];
__device__ __nv_bfloat16  g_wout_hi[(size_t)DIM * DIM];
__device__ __nv_bfloat16  g_wout_lo[(size_t)DIM * DIM];
__device__ __nv_bfloat16  g_att_hi[(size_t)MTOK * EO];
__device__ __nv_bfloat16  g_att_lo[(size_t)MTOK * EO];

// ---------------- helpers ---------------------------------------------------
__device__ __forceinline__ uint32_t smem_u32(const void* p) {
    uint32_t a;
    asm("{ .reg .u64 t; cvta.to.shared.u64 t, %1; cvt.u32.u64 %0, t; }" : "=r"(a) : "l"(p));
    return a;
}

// SW64 swizzle: 64-byte rows, 8-row/512B atom
#define SWZ64(off) ((off) ^ (((off) >> 3) & 0x30))

__device__ __forceinline__ void cp16(uint32_t saddr, const void* g) {
    asm volatile("cp.async.cg.shared.global [%0], [%1], 16;" :: "r"(saddr), "l"(g));
}
#define CP_COMMIT() asm volatile("cp.async.commit_group;" ::: "memory")
#define CP_WAIT4()  asm volatile("cp.async.wait_group 4;" ::: "memory")

__device__ __forceinline__ void ldm_x4(uint32_t* r, uint32_t addr) {
    asm volatile("ldmatrix.sync.aligned.m8n8.x4.shared.b16 {%0,%1,%2,%3}, [%4];"
                 : "=r"(r[0]), "=r"(r[1]), "=r"(r[2]), "=r"(r[3]) : "r"(addr));
}

__device__ __forceinline__ void mma16816(float* d, const uint32_t* a, const uint32_t* b) {
    asm volatile("mma.sync.aligned.m16n8k16.row.col.f32.bf16.bf16.f32 "
                 "{%0,%1,%2,%3}, {%4,%5,%6,%7}, {%8,%9}, {%0,%1,%2,%3};"
                 : "+f"(d[0]), "+f"(d[1]), "+f"(d[2]), "+f"(d[3])
                 : "r"(a[0]), "r"(a[1]), "r"(a[2]), "r"(a[3]), "r"(b[0]), "r"(b[1]));
}

// ---------------------------------------------------------------------------
// split: fp32 -> bf16 hi + bf16 lo (residual)
// ---------------------------------------------------------------------------
__global__ void __launch_bounds__(256)
split_kernel(const float* __restrict__ in, __nv_bfloat16* __restrict__ hi,
             __nv_bfloat16* __restrict__ lo, int n4)
{
    int i = blockIdx.x * 256 + threadIdx.x;
    if (i >= n4) return;
    float4 v = ((const float4*)in)[i];
    __nv_bfloat16 h[4], l[4];
    float f[4] = {v.x, v.y, v.z, v.w};
#pragma unroll
    for (int j = 0; j < 4; j++) {
        h[j] = __float2bfloat16(f[j]);
        l[j] = __float2bfloat16(f[j] - __bfloat162float(h[j]));
    }
    ((uint64_t*)hi)[i] = *(const uint64_t*)h;
    ((uint64_t*)lo)[i] = *(const uint64_t*)l;
}

// ---------------------------------------------------------------------------
// FUSED bf16 3-term split GEMM on mma.sync: C[M,N] = A x B^T (+bias)
// 512 threads (16 warps, 4m x 4n, warp tile 32x32), CTA tile 128x128, BK=32.
// Per chunk: ALL fragments hoisted (64 regs) -> 48-deep independent mma chain
// per warp. 6-stage cp.async ring (192KB), 1 CTA/SM.
// Terms: ah*bh + al*bh + ah*bl.
// ---------------------------------------------------------------------------
#define GBK      32
#define SUB_A_LO 8192
#define SUB_B_HI 16384
#define SUB_B_LO 24576
#define STAGE_SZ 32768
#define NSTAGE   6
#define GSMEM_SZ (NSTAGE * STAGE_SZ)   // 196608

__device__ __forceinline__ void fill_chunk(
    int cc, uint32_t dst, int tid, int m0, int n0, int K,
    const __nv_bfloat16* __restrict__ Ahi, const __nv_bfloat16* __restrict__ Alo,
    const __nv_bfloat16* __restrict__ Bhi, const __nv_bfloat16* __restrict__ Blo)
{
    const int kk = cc * GBK;
    const int row = tid >> 2, c16 = tid & 3;       // 512 16B units per sub-tile
    const uint32_t so = SWZ64((uint32_t)(row * 64 + c16 * 16));
    const size_t aoff = (size_t)(m0 + row) * K + kk + c16 * 8;
    const size_t boff = (size_t)(n0 + row) * K + kk + c16 * 8;
    cp16(dst + so,            Ahi + aoff);
    cp16(dst + SUB_A_LO + so, Alo + aoff);
    cp16(dst + SUB_B_HI + so, Bhi + boff);
    cp16(dst + SUB_B_LO + so, Blo + boff);
}

__global__ void __launch_bounds__(512, 1)
gemm_bf16x3(const __nv_bfloat16* __restrict__ Ahi, const __nv_bfloat16* __restrict__ Alo,
            const __nv_bfloat16* __restrict__ Bhi, const __nv_bfloat16* __restrict__ Blo,
            float* __restrict__ C, const float* __restrict__ bias, int N, int K)
{
    extern __shared__ char smem[];
    const uint32_t sb = smem_u32(smem);
    const int tid = threadIdx.x;
    const int m0 = blockIdx.y * 128;
    const int n0 = blockIdx.x * 128;
    const int lane = tid & 31;
    const int warp = tid >> 5;         // 0..15
    const int warp_m = warp >> 2;      // 0..3 (32 rows each)
    const int warp_n = warp & 3;       // 0..3 (32 cols each)

    float acc[2][4][4];
#pragma unroll
    for (int a = 0; a < 2; a++)
#pragma unroll
        for (int b = 0; b < 4; b++)
#pragma unroll
            for (int c = 0; c < 4; c++) acc[a][b][c] = 0.f;

    const int kchunks = K / GBK;       // 32

    // prologue: fill stages 0..4
#pragma unroll
    for (int p = 0; p < NSTAGE - 1; p++) {
        fill_chunk(p, sb + (uint32_t)p * STAGE_SZ, tid, m0, n0, K, Ahi, Alo, Bhi, Blo);
        CP_COMMIT();
    }

    // ldmatrix per-thread address components (pre-swizzle byte offsets, 64B rows)
    const uint32_t a_row_half = (uint32_t)(lane & 15);
    const uint32_t a_koff     = (uint32_t)((lane >> 4) << 4);
    const uint32_t b_row_half = (uint32_t)(((lane >> 4) << 3) + (lane & 7));
    const uint32_t b_koff     = (uint32_t)(((lane >> 3) & 1) << 4);

    for (int cc = 0; cc < kchunks; cc++) {
        CP_WAIT4();                    // chunks <= cc complete (commit-per-iter keeps count)
        __syncthreads();               // all warps done reading stage (cc-1)%6
        if (cc + NSTAGE - 1 < kchunks)
            fill_chunk(cc + NSTAGE - 1,
                       sb + (uint32_t)((cc + NSTAGE - 1) % NSTAGE) * STAGE_SZ,
                       tid, m0, n0, K, Ahi, Alo, Bhi, Blo);
        CP_COMMIT();                   // commit every iteration (may be empty)

        const uint32_t st = sb + (uint32_t)(cc % NSTAGE) * STAGE_SZ;

        // hoist ALL fragments for this chunk
        uint32_t ah[2][2][4], al[2][2][4], bh[2][2][4], bl[2][2][4];
#pragma unroll
        for (int ks = 0; ks < 2; ks++) {
            const uint32_t kbyte = (uint32_t)(ks * 32);
#pragma unroll
            for (int mt = 0; mt < 2; mt++) {
                const uint32_t row = (uint32_t)(warp_m * 32 + mt * 16) + a_row_half;
                const uint32_t so = SWZ64(row * 64 + kbyte + a_koff);
                ldm_x4(ah[ks][mt], st + so);
                ldm_x4(al[ks][mt], st + SUB_A_LO + so);
            }
#pragma unroll
            for (int nt2 = 0; nt2 < 2; nt2++) {
                const uint32_t row = (uint32_t)(warp_n * 32 + nt2 * 16) + b_row_half;
                const uint32_t so = SWZ64(row * 64 + kbyte + b_koff);
                ldm_x4(bh[ks][nt2], st + SUB_B_HI + so);
                ldm_x4(bl[ks][nt2], st + SUB_B_LO + so);
            }
        }
        // 48-deep mma chain, no smem dependencies
#pragma unroll
        for (int ks = 0; ks < 2; ks++)
#pragma unroll
            for (int mt = 0; mt < 2; mt++)
#pragma unroll
                for (int nt = 0; nt < 4; nt++) {
                    const uint32_t* bph = &bh[ks][nt >> 1][(nt & 1) * 2];
                    const uint32_t* bpl = &bl[ks][nt >> 1][(nt & 1) * 2];
                    mma16816(acc[mt][nt], ah[ks][mt], bph);
                    mma16816(acc[mt][nt], al[ks][mt], bph);
                    mma16816(acc[mt][nt], ah[ks][mt], bpl);
                }
    }

    __syncthreads();

    // epilogue
    const int ln4 = lane >> 2;
    const int lc2 = (lane & 3) * 2;
#pragma unroll
    for (int mt = 0; mt < 2; mt++) {
        const int r0 = m0 + warp_m * 32 + mt * 16 + ln4;
#pragma unroll
        for (int nt = 0; nt < 4; nt++) {
            const int col = n0 + warp_n * 32 + nt * 8 + lc2;
            float bx = 0.f, by = 0.f;
            if (bias) { bx = bias[col]; by = bias[col + 1]; }
            float2 v0 = make_float2(acc[mt][nt][0] + bx, acc[mt][nt][1] + by);
            float2 v1 = make_float2(acc[mt][nt][2] + bx, acc[mt][nt][3] + by);
            *(float2*)(C + (size_t)r0 * N + col)       = v0;
            *(float2*)(C + (size_t)(r0 + 8) * N + col) = v1;
        }
    }
}

// ---------------------------------------------------------------------------
// Attention: one block per (sequence, head). Writes bf16 hi/lo split output.
// ---------------------------------------------------------------------------
__global__ void __launch_bounds__(256)
attn_kernel(const float* __restrict__ qkv,
            __nv_bfloat16* __restrict__ att_hi, __nv_bfloat16* __restrict__ att_lo)
{
    const int blk  = blockIdx.x;
    const int head = blk & 15;
    const int n    = blk >> 4;
    const int b    = n / HWP;
    const int hw   = n - b * HWP;
    const size_t base_tok = (size_t)b * (TT * HWP) + hw;

    __shared__ float Qs[32][65];
    __shared__ float Ks[32][65];
    __shared__ float Vs[32][64];
    __shared__ float Ss[32][33];

    const int tid = threadIdx.x;

    for (int i = tid; i < 32 * 64; i += 256) {
        const int t = i >> 6, d = i & 63;
        const size_t tok = base_tok + (size_t)t * HWP;
        const float* p = qkv + tok * EQKV + head * HD + d;
        Qs[t][d] = p[0];
        Ks[t][d] = p[1024];
        Vs[t][d] = p[2048];
    }
    __syncthreads();

    for (int i = tid; i < 2 * 32 * 16; i += 256) {
        const int mat = i >> 9;
        const int rem = i & 511;
        const int t = rem >> 4, j = rem & 15;
        const float freq = powf(10000.0f, -(float)j / 16.0f);
        const float ang = (float)t * freq;
        const float c = cosf(ang), s = sinf(ang);
        float (*P)[65] = mat ? Ks : Qs;
        const float x0 = P[t][2 * j];
        const float x1 = P[t][2 * j + 1];
        P[t][2 * j]     = x0 * c - x1 * s;
        P[t][2 * j + 1] = x1 * c + x0 * s;
    }
    __syncthreads();

    const int r = tid >> 4, c = tid & 15;
    {
        float s00 = 0.f, s01 = 0.f, s10 = 0.f, s11 = 0.f;
#pragma unroll 16
        for (int d = 0; d < 64; d++) {
            const float q0 = Qs[2 * r][d],     q1 = Qs[2 * r + 1][d];
            const float k0 = Ks[2 * c][d],     k1 = Ks[2 * c + 1][d];
            s00 += q0 * k0; s01 += q0 * k1;
            s10 += q1 * k0; s11 += q1 * k1;
        }
        Ss[2 * r][2 * c]         = s00;
        Ss[2 * r][2 * c + 1]     = s01;
        Ss[2 * r + 1][2 * c]     = s10;
        Ss[2 * r + 1][2 * c + 1] = s11;
    }
    __syncthreads();

    const int warp = tid >> 5, lane = tid & 31;
    const float scale = 0.125f;
#pragma unroll
    for (int qi = 0; qi < 4; qi++) {
        const int q = warp * 4 + qi;
        float s = (lane <= q) ? Ss[q][lane] * scale : -INFINITY;
        float m = s;
#pragma unroll
        for (int o = 16; o > 0; o >>= 1)
            m = fmaxf(m, __shfl_xor_sync(0xffffffffu, m, o));
        const float e = expf(s - m);
        float sum = e;
#pragma unroll
        for (int o = 16; o > 0; o >>= 1)
            sum += __shfl_xor_sync(0xffffffffu, sum, o);
        Ss[q][lane] = e / sum;
    }
    __syncthreads();

    float o0[4] = {0.f, 0.f, 0.f, 0.f};
    float o1[4] = {0.f, 0.f, 0.f, 0.f};
#pragma unroll 8
    for (int k = 0; k < 32; k++) {
        const float p0 = Ss[2 * r][k];
        const float p1 = Ss[2 * r + 1][k];
#pragma unroll
        for (int j = 0; j < 4; j++) {
            const float v = Vs[k][4 * c + j];
            o0[j] += p0 * v;
            o1[j] += p1 * v;
        }
    }
#pragma unroll
    for (int i = 0; i < 2; i++) {
        const int t = 2 * r + i;
        const size_t tok = base_tok + (size_t)t * HWP;
        const size_t base = tok * EO + head * HD + 4 * c;
        const float* src = i ? o1 : o0;
        __nv_bfloat16 h[4], l[4];
#pragma unroll
        for (int j = 0; j < 4; j++) {
            h[j] = __float2bfloat16(src[j]);
            l[j] = __float2bfloat16(src[j] - __bfloat162float(h[j]));
        }
        *(uint64_t*)(att_hi + base) = *(const uint64_t*)h;
        *(uint64_t*)(att_lo + base) = *(const uint64_t*)l;
    }
}

// ---------------------------------------------------------------------------
extern "C" void kernel_launch(void* const* d_in, const int* in_sizes, int n_in,
                              void* d_out, int out_size)
{
    const float* x     = (const float*)d_in[0];
    const float* w_qkv = (const float*)d_in[1];
    const float* w_out = (const float*)d_in[2];
    const float* b_out = (const float*)d_in[3];
    float* out = (float*)d_out;

    void *qkv_p, *xh_p, *xl_p, *wqh_p, *wql_p, *woh_p, *wol_p, *ah_p, *al_p;
    cudaGetSymbolAddress(&qkv_p, g_qkv);
    cudaGetSymbolAddress(&xh_p,  g_x_hi);    cudaGetSymbolAddress(&xl_p,  g_x_lo);
    cudaGetSymbolAddress(&wqh_p, g_wqkv_hi); cudaGetSymbolAddress(&wql_p, g_wqkv_lo);
    cudaGetSymbolAddress(&woh_p, g_wout_hi); cudaGetSymbolAddress(&wol_p, g_wout_lo);
    cudaGetSymbolAddress(&ah_p,  g_att_hi);  cudaGetSymbolAddress(&al_p,  g_att_lo);

    float* qkv = (float*)qkv_p;
    __nv_bfloat16 *xh = (__nv_bfloat16*)xh_p, *xl = (__nv_bfloat16*)xl_p;
    __nv_bfloat16 *wqh = (__nv_bfloat16*)wqh_p, *wql = (__nv_bfloat16*)wql_p;
    __nv_bfloat16 *woh = (__nv_bfloat16*)woh_p, *wol = (__nv_bfloat16*)wol_p;
    __nv_bfloat16 *ah = (__nv_bfloat16*)ah_p, *al = (__nv_bfloat16*)al_p;

    cudaFuncSetAttribute(gemm_bf16x3, cudaFuncAttributeMaxDynamicSharedMemorySize, GSMEM_SZ);

    // 0) split inputs into bf16 hi/lo
    {
        int n4 = (MTOK * DIM) / 4;
        split_kernel<<<(n4 + 255) / 256, 256>>>(x, xh, xl, n4);
        n4 = (EQKV * DIM) / 4;
        split_kernel<<<(n4 + 255) / 256, 256>>>(w_qkv, wqh, wql, n4);
        n4 = (DIM * DIM) / 4;
        split_kernel<<<(n4 + 255) / 256, 256>>>(w_out, woh, wol, n4);
    }
    // 1) QKV projection: [36864,1024] x [3072,1024]^T
    {
        dim3 grid(EQKV / 128, MTOK / 128);
        gemm_bf16x3<<<grid, 512, GSMEM_SZ>>>(xh, xl, wqh, wql, qkv, nullptr, EQKV, DIM);
    }
    // 2) RoPE + causal attention, writes split bf16 att
    {
        attn_kernel<<<(BB * HWP) * HEADS, 256>>>(qkv, ah, al);
    }
    // 3) Output projection + bias
    {
        dim3 grid(DIM / 128, MTOK / 128);
        gemm_bf16x3<<<grid, 512, GSMEM_SZ>>>(ah, al, woh, wol, out, b_out, DIM, DIM);
    }
}

// round 12
// speedup vs baseline: 3.9667x; 1.6616x over previous
#include <cuda_runtime.h>
#include <cuda_fp16.h>
#include <cstdint>
#include <math.h>

// Problem constants
#define BB    2
#define TT    32
#define HH    18
#define WW    32
#define DIM   1024
#define HEADS 16
#define HD    64
#define HWP   (HH*WW)            // 576
#define MTOK  (BB*TT*HWP)        // 36864 tokens
#define EQKV  (3*HEADS*HD)       // 3072
#define EO    (HEADS*HD)         // 1024

// ---------------- scratch (device globals; no allocation allowed) ----------
__device__ float   g_qkv[(size_t)MTOK * EQKV];
__device__ __half  g_x_hi[(size_t)MTOK * DIM];
__device__ __half  g_x_lo[(size_t)MTOK * DIM];
__device__ __half  g_wq[(size_t)EQKV * DIM];
__device__ __half  g_wo[(size_t)DIM * DIM];
__device__ __half  g_att_hi[(size_t)MTOK * EO];
__device__ __half  g_att_lo[(size_t)MTOK * EO];

// ---------------- helpers ---------------------------------------------------
__device__ __forceinline__ uint32_t smem_u32(const void* p) {
    uint32_t a;
    asm("{ .reg .u64 t; cvta.to.shared.u64 t, %1; cvt.u32.u64 %0, t; }" : "=r"(a) : "l"(p));
    return a;
}

// SW64 swizzle: 64-byte rows, 8-row/512B atom
#define SWZ64(off) ((off) ^ (((off) >> 3) & 0x30))

__device__ __forceinline__ void cp16(uint32_t saddr, const void* g) {
    asm volatile("cp.async.cg.shared.global [%0], [%1], 16;" :: "r"(saddr), "l"(g));
}
#define CP_COMMIT() asm volatile("cp.async.commit_group;" ::: "memory")
#define CP_WAIT0()  asm volatile("cp.async.wait_group 0;" ::: "memory")
#define CP_WAIT1()  asm volatile("cp.async.wait_group 1;" ::: "memory")

__device__ __forceinline__ void ldm_x4(uint32_t* r, uint32_t addr) {
    asm volatile("ldmatrix.sync.aligned.m8n8.x4.shared.b16 {%0,%1,%2,%3}, [%4];"
                 : "=r"(r[0]), "=r"(r[1]), "=r"(r[2]), "=r"(r[3]) : "r"(addr));
}

__device__ __forceinline__ void mma_f16(float* d, const uint32_t* a, const uint32_t* b) {
    asm volatile("mma.sync.aligned.m16n8k16.row.col.f32.f16.f16.f32 "
                 "{%0,%1,%2,%3}, {%4,%5,%6,%7}, {%8,%9}, {%0,%1,%2,%3};"
                 : "+f"(d[0]), "+f"(d[1]), "+f"(d[2]), "+f"(d[3])
                 : "r"(a[0]), "r"(a[1]), "r"(a[2]), "r"(a[3]), "r"(b[0]), "r"(b[1]));
}

// ---------------------------------------------------------------------------
// split2: fp32 -> fp16 hi + fp16 lo (residual)
// ---------------------------------------------------------------------------
__global__ void __launch_bounds__(256)
split2_kernel(const float* __restrict__ in, __half* __restrict__ hi,
              __half* __restrict__ lo, int n4)
{
    int i = blockIdx.x * 256 + threadIdx.x;
    if (i >= n4) return;
    float4 v = ((const float4*)in)[i];
    __half h[4], l[4];
    float f[4] = {v.x, v.y, v.z, v.w};
#pragma unroll
    for (int j = 0; j < 4; j++) {
        h[j] = __float2half(f[j]);
        l[j] = __float2half(f[j] - __half2float(h[j]));
    }
    ((uint64_t*)hi)[i] = *(const uint64_t*)h;
    ((uint64_t*)lo)[i] = *(const uint64_t*)l;
}

// ---------------------------------------------------------------------------
// cvt: fp32 -> fp16
// ---------------------------------------------------------------------------
__global__ void __launch_bounds__(256)
cvt_kernel(const float* __restrict__ in, __half* __restrict__ out, int n4)
{
    int i = blockIdx.x * 256 + threadIdx.x;
    if (i >= n4) return;
    float4 v = ((const float4*)in)[i];
    __half h[4] = {__float2half(v.x), __float2half(v.y),
                   __float2half(v.z), __float2half(v.w)};
    ((uint64_t*)out)[i] = *(const uint64_t*)h;
}

// ---------------------------------------------------------------------------
// FUSED fp16 2-term split GEMM on mma.sync: C = (Ahi+Alo) x B^T (+bias)
// R9 structure: CTA tile 128x128, BK=32 (64B rows, SW64), 8 warps (2m x 4n),
// warp tile 64x32, 3-stage cp.async ring (72KB) -> 2 CTAs/SM.
// Terms per fragment: ah*b + al*b (2 mmas).
// ---------------------------------------------------------------------------
#define GBK      32
#define SUB_A_LO 8192
#define SUB_B    16384
#define STAGE_SZ 24576
#define NSTAGE   3
#define GSMEM_SZ (NSTAGE * STAGE_SZ)   // 73728 per CTA

__device__ __forceinline__ void fill_chunk(
    int cc, uint32_t dst, int tid, int m0, int n0, int K,
    const __half* __restrict__ Ahi, const __half* __restrict__ Alo,
    const __half* __restrict__ B)
{
    const int kk = cc * GBK;
#pragma unroll
    for (int i = 0; i < 2; i++) {
        const int u = tid + i * 256;             // 512 16B-units per sub-tile
        const int row = u >> 2, c16 = u & 3;     // 4 units per 64B row
        const uint32_t so = SWZ64((uint32_t)(row * 64 + c16 * 16));
        const size_t aoff = (size_t)(m0 + row) * K + kk + c16 * 8;
        const size_t boff = (size_t)(n0 + row) * K + kk + c16 * 8;
        cp16(dst + so,            Ahi + aoff);
        cp16(dst + SUB_A_LO + so, Alo + aoff);
        cp16(dst + SUB_B + so,    B + boff);
    }
}

__global__ void __launch_bounds__(256, 2)
gemm_f16x2(const __half* __restrict__ Ahi, const __half* __restrict__ Alo,
           const __half* __restrict__ B,
           float* __restrict__ C, const float* __restrict__ bias, int N, int K)
{
    extern __shared__ char smem[];
    const uint32_t sb = smem_u32(smem);
    const int tid = threadIdx.x;
    const int m0 = blockIdx.y * 128;
    const int n0 = blockIdx.x * 128;
    const int lane = tid & 31;
    const int warp = tid >> 5;
    const int warp_m = warp >> 2;      // 0..1
    const int warp_n = warp & 3;       // 0..3

    float acc[4][4][4];
#pragma unroll
    for (int a = 0; a < 4; a++)
#pragma unroll
        for (int b = 0; b < 4; b++)
#pragma unroll
            for (int c = 0; c < 4; c++) acc[a][b][c] = 0.f;

    const int kchunks = K / GBK;       // 32

    fill_chunk(0, sb, tid, m0, n0, K, Ahi, Alo, B);
    CP_COMMIT();
    fill_chunk(1, sb + STAGE_SZ, tid, m0, n0, K, Ahi, Alo, B);
    CP_COMMIT();

    // ldmatrix per-thread address components (pre-swizzle byte offsets, 64B rows)
    const uint32_t a_row_half = (uint32_t)(lane & 15);
    const uint32_t a_koff     = (uint32_t)((lane >> 4) << 4);
    const uint32_t b_row_half = (uint32_t)(((lane >> 4) << 3) + (lane & 7));
    const uint32_t b_koff     = (uint32_t)(((lane >> 3) & 1) << 4);

    for (int cc = 0; cc < kchunks; cc++) {
        if (cc + 1 < kchunks) { CP_WAIT1(); } else { CP_WAIT0(); }
        __syncthreads();
        if (cc + 2 < kchunks) {
            fill_chunk(cc + 2, sb + (uint32_t)((cc + 2) % NSTAGE) * STAGE_SZ,
                       tid, m0, n0, K, Ahi, Alo, B);
            CP_COMMIT();
        }
        const uint32_t st = sb + (uint32_t)(cc % NSTAGE) * STAGE_SZ;

#pragma unroll
        for (int ks = 0; ks < 2; ks++) {
            uint32_t bf[2][4];
#pragma unroll
            for (int nt2 = 0; nt2 < 2; nt2++) {
                const uint32_t row = (uint32_t)(warp_n * 32 + nt2 * 16) + b_row_half;
                const uint32_t so = SWZ64(row * 64 + (uint32_t)(ks * 32) + b_koff);
                ldm_x4(bf[nt2], st + SUB_B + so);
            }
#pragma unroll
            for (int mt = 0; mt < 4; mt++) {
                uint32_t ah[4], al[4];
                const uint32_t row = (uint32_t)(warp_m * 64 + mt * 16) + a_row_half;
                const uint32_t so = SWZ64(row * 64 + (uint32_t)(ks * 32) + a_koff);
                ldm_x4(ah, st + so);
                ldm_x4(al, st + SUB_A_LO + so);
#pragma unroll
                for (int nt = 0; nt < 4; nt++) {
                    const uint32_t* bp = &bf[nt >> 1][(nt & 1) * 2];
                    mma_f16(acc[mt][nt], ah, bp);
                    mma_f16(acc[mt][nt], al, bp);
                }
            }
        }
    }

    __syncthreads();

    // epilogue
    const int ln4 = lane >> 2;
    const int lc2 = (lane & 3) * 2;
#pragma unroll
    for (int mt = 0; mt < 4; mt++) {
        const int r0 = m0 + warp_m * 64 + mt * 16 + ln4;
#pragma unroll
        for (int nt = 0; nt < 4; nt++) {
            const int col = n0 + warp_n * 32 + nt * 8 + lc2;
            float bx = 0.f, by = 0.f;
            if (bias) { bx = bias[col]; by = bias[col + 1]; }
            float2 v0 = make_float2(acc[mt][nt][0] + bx, acc[mt][nt][1] + by);
            float2 v1 = make_float2(acc[mt][nt][2] + bx, acc[mt][nt][3] + by);
            *(float2*)(C + (size_t)r0 * N + col)       = v0;
            *(float2*)(C + (size_t)(r0 + 8) * N + col) = v1;
        }
    }
}

// ---------------------------------------------------------------------------
// Attention: one block per (sequence, head). Writes fp16 hi/lo split output.
// ---------------------------------------------------------------------------
__global__ void __launch_bounds__(256)
attn_kernel(const float* __restrict__ qkv,
            __half* __restrict__ att_hi, __half* __restrict__ att_lo)
{
    const int blk  = blockIdx.x;
    const int head = blk & 15;
    const int n    = blk >> 4;
    const int b    = n / HWP;
    const int hw   = n - b * HWP;
    const size_t base_tok = (size_t)b * (TT * HWP) + hw;

    __shared__ float Qs[32][65];
    __shared__ float Ks[32][65];
    __shared__ float Vs[32][64];
    __shared__ float Ss[32][33];

    const int tid = threadIdx.x;

    for (int i = tid; i < 32 * 64; i += 256) {
        const int t = i >> 6, d = i & 63;
        const size_t tok = base_tok + (size_t)t * HWP;
        const float* p = qkv + tok * EQKV + head * HD + d;
        Qs[t][d] = p[0];
        Ks[t][d] = p[1024];
        Vs[t][d] = p[2048];
    }
    __syncthreads();

    for (int i = tid; i < 2 * 32 * 16; i += 256) {
        const int mat = i >> 9;
        const int rem = i & 511;
        const int t = rem >> 4, j = rem & 15;
        const float freq = powf(10000.0f, -(float)j / 16.0f);
        const float ang = (float)t * freq;
        const float c = cosf(ang), s = sinf(ang);
        float (*P)[65] = mat ? Ks : Qs;
        const float x0 = P[t][2 * j];
        const float x1 = P[t][2 * j + 1];
        P[t][2 * j]     = x0 * c - x1 * s;
        P[t][2 * j + 1] = x1 * c + x0 * s;
    }
    __syncthreads();

    const int r = tid >> 4, c = tid & 15;
    {
        float s00 = 0.f, s01 = 0.f, s10 = 0.f, s11 = 0.f;
#pragma unroll 16
        for (int d = 0; d < 64; d++) {
            const float q0 = Qs[2 * r][d],     q1 = Qs[2 * r + 1][d];
            const float k0 = Ks[2 * c][d],     k1 = Ks[2 * c + 1][d];
            s00 += q0 * k0; s01 += q0 * k1;
            s10 += q1 * k0; s11 += q1 * k1;
        }
        Ss[2 * r][2 * c]         = s00;
        Ss[2 * r][2 * c + 1]     = s01;
        Ss[2 * r + 1][2 * c]     = s10;
        Ss[2 * r + 1][2 * c + 1] = s11;
    }
    __syncthreads();

    const int warp = tid >> 5, lane = tid & 31;
    const float scale = 0.125f;
#pragma unroll
    for (int qi = 0; qi < 4; qi++) {
        const int q = warp * 4 + qi;
        float s = (lane <= q) ? Ss[q][lane] * scale : -INFINITY;
        float m = s;
#pragma unroll
        for (int o = 16; o > 0; o >>= 1)
            m = fmaxf(m, __shfl_xor_sync(0xffffffffu, m, o));
        const float e = expf(s - m);
        float sum = e;
#pragma unroll
        for (int o = 16; o > 0; o >>= 1)
            sum += __shfl_xor_sync(0xffffffffu, sum, o);
        Ss[q][lane] = e / sum;
    }
    __syncthreads();

    float o0[4] = {0.f, 0.f, 0.f, 0.f};
    float o1[4] = {0.f, 0.f, 0.f, 0.f};
#pragma unroll 8
    for (int k = 0; k < 32; k++) {
        const float p0 = Ss[2 * r][k];
        const float p1 = Ss[2 * r + 1][k];
#pragma unroll
        for (int j = 0; j < 4; j++) {
            const float v = Vs[k][4 * c + j];
            o0[j] += p0 * v;
            o1[j] += p1 * v;
        }
    }
#pragma unroll
    for (int i = 0; i < 2; i++) {
        const int t = 2 * r + i;
        const size_t tok = base_tok + (size_t)t * HWP;
        const size_t base = tok * EO + head * HD + 4 * c;
        const float* src = i ? o1 : o0;
        __half h[4], l[4];
#pragma unroll
        for (int j = 0; j < 4; j++) {
            h[j] = __float2half(src[j]);
            l[j] = __float2half(src[j] - __half2float(h[j]));
        }
        *(uint64_t*)(att_hi + base) = *(const uint64_t*)h;
        *(uint64_t*)(att_lo + base) = *(const uint64_t*)l;
    }
}

// ---------------------------------------------------------------------------
extern "C" void kernel_launch(void* const* d_in, const int* in_sizes, int n_in,
                              void* d_out, int out_size)
{
    const float* x     = (const float*)d_in[0];
    const float* w_qkv = (const float*)d_in[1];
    const float* w_out = (const float*)d_in[2];
    const float* b_out = (const float*)d_in[3];
    float* out = (float*)d_out;

    void *qkv_p, *xh_p, *xl_p, *wq_p, *wo_p, *ah_p, *al_p;
    cudaGetSymbolAddress(&qkv_p, g_qkv);
    cudaGetSymbolAddress(&xh_p,  g_x_hi);   cudaGetSymbolAddress(&xl_p,  g_x_lo);
    cudaGetSymbolAddress(&wq_p,  g_wq);     cudaGetSymbolAddress(&wo_p,  g_wo);
    cudaGetSymbolAddress(&ah_p,  g_att_hi); cudaGetSymbolAddress(&al_p,  g_att_lo);

    float* qkv = (float*)qkv_p;
    __half *xh = (__half*)xh_p, *xl = (__half*)xl_p;
    __half *wq = (__half*)wq_p, *wo = (__half*)wo_p;
    __half *ah = (__half*)ah_p, *al = (__half*)al_p;

    cudaFuncSetAttribute(gemm_f16x2, cudaFuncAttributeMaxDynamicSharedMemorySize, GSMEM_SZ);

    // 0) split x into fp16 hi/lo; convert weights to fp16
    {
        int n4 = (MTOK * DIM) / 4;
        split2_kernel<<<(n4 + 255) / 256, 256>>>(x, xh, xl, n4);
        n4 = (EQKV * DIM) / 4;
        cvt_kernel<<<(n4 + 255) / 256, 256>>>(w_qkv, wq, n4);
        n4 = (DIM * DIM) / 4;
        cvt_kernel<<<(n4 + 255) / 256, 256>>>(w_out, wo, n4);
    }
    // 1) QKV projection: [36864,1024] x [3072,1024]^T
    {
        dim3 grid(EQKV / 128, MTOK / 128);
        gemm_f16x2<<<grid, 256, GSMEM_SZ>>>(xh, xl, wq, qkv, nullptr, EQKV, DIM);
    }
    // 2) RoPE + causal attention, writes split fp16 att
    {
        attn_kernel<<<(BB * HWP) * HEADS, 256>>>(qkv, ah, al);
    }
    // 3) Output projection + bias
    {
        dim3 grid(DIM / 128, MTOK / 128);
        gemm_f16x2<<<grid, 256, GSMEM_SZ>>>(ah, al, wo, out, b_out, DIM, DIM);
    }
}